// round 10
// baseline (speedup 1.0000x reference)
#include <cuda_runtime.h>
#include <cstdint>

#define SS   192
#define SPAD 193          // odd stride -> conflict-free column access
#define CS   8            // CTAs per batch (cluster)
#define NT   768          // 24 warps: >= max cells/CTA per width (ceil(191/8)=24)
#define NEGINF (-1e30f)

__device__ __forceinline__ float fsoftplus(float x) {
    return fmaxf(x, 0.f) + __logf(1.f + __expf(-fabsf(x)));
}
__device__ __forceinline__ uint32_t smem_u32(const void* p) {
    return (uint32_t)__cvta_generic_to_shared(p);
}
// store v into CTA `peer`'s smem at the same offset as local addr
__device__ __forceinline__ void st_peer(uint32_t laddr, int peer, float v) {
    uint32_t ra;
    asm volatile("mapa.shared::cluster.u32 %0, %1, %2;" : "=r"(ra) : "r"(laddr), "r"(peer));
    asm volatile("st.shared::cluster.f32 [%0], %1;" :: "r"(ra), "f"(v) : "memory");
}
__device__ __forceinline__ void cluster_bar() {
    asm volatile("barrier.cluster.arrive.aligned;" ::: "memory");
    asm volatile("barrier.cluster.wait.aligned;"   ::: "memory");
}

extern __shared__ float C[];   // [SS][SPAD]; upper tri = inside a, lower tri = q (bwd)

__global__ void __cluster_dims__(CS, 1, 1) __launch_bounds__(NT, 1)
cky_kernel(const float* __restrict__ rules, const int* __restrict__ lens,
           float* __restrict__ Zout, float* __restrict__ marg)
{
    const int b = blockIdx.x / CS;
    int rank; asm("mov.u32 %0, %%cluster_ctarank;" : "=r"(rank));
    const float* __restrict__ R = rules + (size_t)b * SS * SS;
    float* __restrict__ M = marg + (size_t)b * SS * SS;
    const int tid = threadIdx.x, lane = tid & 31, wid = tid >> 5;
    const int L = lens[b];

    // zero marginal slab cooperatively (lower triangle / untouched cells must be 0)
    for (int t = rank * NT + tid; t < SS * SS; t += CS * NT) M[t] = 0.f;
    // diagonal init: redundant in every CTA (identical, deterministic)
    for (int i = tid; i < SS; i += NT) C[i * SPAD + i] = fsoftplus(R[i * SS + i]);
    __syncthreads();

    // ---------------- forward (inside), increasing width ----------------
    for (int w = 1; w < SS; ++w) {
        const int n  = SS - w;
        const int cb = (n * rank) / CS, ce = (n * (rank + 1)) / CS;  // cell slice, <=24
        const int c  = cb + wid;                                     // warp per cell, 1 pass
        if (c < ce) {
            const int i = c, j = c + w;
            const float rv = R[i * SS + j];           // prefetch (hides L2 latency)
            const int nu = (w + 31) >> 5;
            float v[6]; float m = NEGINF;
            #pragma unroll
            for (int u = 0; u < 6; ++u) {
                if (u < nu) {
                    int k = i + lane + (u << 5);
                    float x = (k < j) ? (C[i * SPAD + k] + C[(k + 1) * SPAD + j]) : NEGINF;
                    v[u] = x; m = fmaxf(m, x);
                }
            }
            #pragma unroll
            for (int o = 16; o; o >>= 1) m = fmaxf(m, __shfl_xor_sync(~0u, m, o));
            float s = 0.f;
            #pragma unroll
            for (int u = 0; u < 6; ++u) if (u < nu) s += __expf(v[u] - m);
            #pragma unroll
            for (int o = 16; o; o >>= 1) s += __shfl_xor_sync(~0u, s, o);
            const float val = fsoftplus(rv) + m + __logf(s);
            if (lane < CS) st_peer(smem_u32(&C[i * SPAD + j]), lane, val);  // broadcast
        }
        cluster_bar();
    }

    if (rank == 0 && tid == 0) Zout[b] = C[0 * SPAD + (L - 1)];

    // ---------------- backward (outside / marginals), decreasing width ----------------
    for (int w = SS - 1; w >= 0; --w) {
        const int n  = SS - w;
        const int cb = (n * rank) / CS, ce = (n * (rank + 1)) / CS;
        const int c  = cb + wid;
        if (c < ce) {
            const int i = c, j = c + w;
            const float aij = C[i * SPAD + j];
            const float rv  = R[i * SS + j];
            const int nR = SS - 1 - j;
            float s = 0.f;
            // right-extension parents: a[j+1,j'] + q[i,j']
            for (int t = lane; t < nR; t += 32) {
                const int j2 = j + 1 + t;
                s += __expf(aij + C[(j + 1) * SPAD + j2] + C[j2 * SPAD + i]);
            }
            // left-extension parents: a[i',i-1] + q[i',j]
            for (int t = lane; t < i; t += 32) {
                s += __expf(aij + C[t * SPAD + (i - 1)] + C[j * SPAD + t]);
            }
            #pragma unroll
            for (int o = 16; o; o >>= 1) s += __shfl_xor_sync(~0u, s, o);
            const float g = s + ((i == 0 && j == L - 1) ? 1.f : 0.f);
            if (lane == 0) M[i * SS + j] = g / (1.f + __expf(-rv));   // g * sigmoid(rv)
            if (i < j) {
                const float q = (g > 0.f) ? (__logf(g) - (aij - fsoftplus(rv))) : NEGINF;
                if (lane < CS) st_peer(smem_u32(&C[j * SPAD + i]), lane, q);
            }
        }
        cluster_bar();
    }
}

extern "C" void kernel_launch(void* const* d_in, const int* in_sizes, int n_in,
                              void* d_out, int out_size) {
    const float* rules = (const float*)d_in[0];   // (16,192,192,1) fp32
    const int*   lens  = (const int*)d_in[1];     // (16,) int32
    float* Z = (float*)d_out;                     // first 16 floats
    float* M = (float*)d_out + 16;                // then (16,192,192)

    const int smem = SS * SPAD * (int)sizeof(float);   // 148224 B
    cudaFuncSetAttribute(cky_kernel,
                         cudaFuncAttributeMaxDynamicSharedMemorySize, smem);
    (void)in_sizes; (void)n_in; (void)out_size;

    cky_kernel<<<16 * CS, NT, smem>>>(rules, lens, Z, M);
}

// round 11
// speedup vs baseline: 1.0006x; 1.0006x over previous
#include <cuda_runtime.h>
#include <cstdint>

#define SS   192
#define SPAD 193          // odd stride -> conflict-free column access
#define CS   8            // CTAs per batch (cluster)
#define NT   768          // 24 warps: >= max cells/CTA per width (ceil(191/8)=24)
#define NEGINF (-1e30f)

__device__ __forceinline__ float fsoftplus(float x) {
    return fmaxf(x, 0.f) + __logf(1.f + __expf(-fabsf(x)));
}
__device__ __forceinline__ uint32_t smem_u32(const void* p) {
    return (uint32_t)__cvta_generic_to_shared(p);
}
// store v into CTA `peer`'s smem at the same offset as local addr
__device__ __forceinline__ void st_peer(uint32_t laddr, int peer, float v) {
    uint32_t ra;
    asm volatile("mapa.shared::cluster.u32 %0, %1, %2;" : "=r"(ra) : "r"(laddr), "r"(peer));
    asm volatile("st.shared::cluster.f32 [%0], %1;" :: "r"(ra), "f"(v) : "memory");
}
__device__ __forceinline__ void cluster_bar() {
    asm volatile("barrier.cluster.arrive.aligned;" ::: "memory");
    asm volatile("barrier.cluster.wait.aligned;"   ::: "memory");
}

extern __shared__ float C[];   // [SS][SPAD]; upper tri = inside a, lower tri = q (bwd)

__global__ void __cluster_dims__(CS, 1, 1) __launch_bounds__(NT, 1)
cky_kernel(const float* __restrict__ rules, const int* __restrict__ lens,
           float* __restrict__ Zout, float* __restrict__ marg)
{
    const int b = blockIdx.x / CS;
    int rank; asm("mov.u32 %0, %%cluster_ctarank;" : "=r"(rank));
    const float* __restrict__ R = rules + (size_t)b * SS * SS;
    float* __restrict__ M = marg + (size_t)b * SS * SS;
    const int tid = threadIdx.x, lane = tid & 31, wid = tid >> 5;
    const int L = lens[b];

    // zero marginal slab cooperatively (lower triangle / untouched cells must be 0)
    for (int t = rank * NT + tid; t < SS * SS; t += CS * NT) M[t] = 0.f;
    // diagonal init: redundant in every CTA (identical, deterministic)
    for (int i = tid; i < SS; i += NT) C[i * SPAD + i] = fsoftplus(R[i * SS + i]);
    __syncthreads();

    // ---------------- forward (inside), increasing width ----------------
    for (int w = 1; w < SS; ++w) {
        const int n  = SS - w;
        const int cb = (n * rank) / CS, ce = (n * (rank + 1)) / CS;  // cell slice, <=24
        const int c  = cb + wid;                                     // warp per cell, 1 pass
        if (c < ce) {
            const int i = c, j = c + w;
            const float rv = R[i * SS + j];           // prefetch (hides L2 latency)
            const int nu = (w + 31) >> 5;
            float v[6]; float m = NEGINF;
            #pragma unroll
            for (int u = 0; u < 6; ++u) {
                if (u < nu) {
                    int k = i + lane + (u << 5);
                    float x = (k < j) ? (C[i * SPAD + k] + C[(k + 1) * SPAD + j]) : NEGINF;
                    v[u] = x; m = fmaxf(m, x);
                }
            }
            #pragma unroll
            for (int o = 16; o; o >>= 1) m = fmaxf(m, __shfl_xor_sync(~0u, m, o));
            float s = 0.f;
            #pragma unroll
            for (int u = 0; u < 6; ++u) if (u < nu) s += __expf(v[u] - m);
            #pragma unroll
            for (int o = 16; o; o >>= 1) s += __shfl_xor_sync(~0u, s, o);
            const float val = fsoftplus(rv) + m + __logf(s);
            if (lane < CS) st_peer(smem_u32(&C[i * SPAD + j]), lane, val);  // broadcast
        }
        cluster_bar();
    }

    if (rank == 0 && tid == 0) Zout[b] = C[0 * SPAD + (L - 1)];

    // ---------------- backward (outside / marginals), decreasing width ----------------
    for (int w = SS - 1; w >= 0; --w) {
        const int n  = SS - w;
        const int cb = (n * rank) / CS, ce = (n * (rank + 1)) / CS;
        const int c  = cb + wid;
        if (c < ce) {
            const int i = c, j = c + w;
            const float aij = C[i * SPAD + j];
            const float rv  = R[i * SS + j];
            const int nR = SS - 1 - j;
            float s = 0.f;
            // right-extension parents: a[j+1,j'] + q[i,j']
            for (int t = lane; t < nR; t += 32) {
                const int j2 = j + 1 + t;
                s += __expf(aij + C[(j + 1) * SPAD + j2] + C[j2 * SPAD + i]);
            }
            // left-extension parents: a[i',i-1] + q[i',j]
            for (int t = lane; t < i; t += 32) {
                s += __expf(aij + C[t * SPAD + (i - 1)] + C[j * SPAD + t]);
            }
            #pragma unroll
            for (int o = 16; o; o >>= 1) s += __shfl_xor_sync(~0u, s, o);
            const float g = s + ((i == 0 && j == L - 1) ? 1.f : 0.f);
            if (lane == 0) M[i * SS + j] = g / (1.f + __expf(-rv));   // g * sigmoid(rv)
            if (i < j) {
                const float q = (g > 0.f) ? (__logf(g) - (aij - fsoftplus(rv))) : NEGINF;
                if (lane < CS) st_peer(smem_u32(&C[j * SPAD + i]), lane, q);
            }
        }
        cluster_bar();
    }
}

extern "C" void kernel_launch(void* const* d_in, const int* in_sizes, int n_in,
                              void* d_out, int out_size) {
    const float* rules = (const float*)d_in[0];   // (16,192,192,1) fp32
    const int*   lens  = (const int*)d_in[1];     // (16,) int32
    float* Z = (float*)d_out;                     // first 16 floats
    float* M = (float*)d_out + 16;                // then (16,192,192)

    const int smem = SS * SPAD * (int)sizeof(float);   // 148224 B
    cudaFuncSetAttribute(cky_kernel,
                         cudaFuncAttributeMaxDynamicSharedMemorySize, smem);
    (void)in_sizes; (void)n_in; (void)out_size;

    cky_kernel<<<16 * CS, NT, smem>>>(rules, lens, Z, M);
}

// round 12
// speedup vs baseline: 1.0008x; 1.0001x over previous
#include <cuda_runtime.h>
#include <cstdint>

#define SS   192
#define SPAD 193          // odd stride -> conflict-free column access
#define CS   8            // CTAs per batch (cluster)
#define NT   768          // 24 warps: >= max cells/CTA per width (ceil(191/8)=24)
#define NEGINF (-1e30f)

__device__ __forceinline__ float fsoftplus(float x) {
    return fmaxf(x, 0.f) + __logf(1.f + __expf(-fabsf(x)));
}
__device__ __forceinline__ uint32_t smem_u32(const void* p) {
    return (uint32_t)__cvta_generic_to_shared(p);
}
// store v into CTA `peer`'s smem at the same offset as local addr
__device__ __forceinline__ void st_peer(uint32_t laddr, int peer, float v) {
    uint32_t ra;
    asm volatile("mapa.shared::cluster.u32 %0, %1, %2;" : "=r"(ra) : "r"(laddr), "r"(peer));
    asm volatile("st.shared::cluster.f32 [%0], %1;" :: "r"(ra), "f"(v) : "memory");
}
__device__ __forceinline__ void cluster_bar() {
    asm volatile("barrier.cluster.arrive.aligned;" ::: "memory");
    asm volatile("barrier.cluster.wait.aligned;"   ::: "memory");
}

extern __shared__ float C[];   // [SS][SPAD]; upper tri = inside a, lower tri = q (bwd)

__global__ void __cluster_dims__(CS, 1, 1) __launch_bounds__(NT, 1)
cky_kernel(const float* __restrict__ rules, const int* __restrict__ lens,
           float* __restrict__ Zout, float* __restrict__ marg)
{
    const int b = blockIdx.x / CS;
    int rank; asm("mov.u32 %0, %%cluster_ctarank;" : "=r"(rank));
    const float* __restrict__ R = rules + (size_t)b * SS * SS;
    float* __restrict__ M = marg + (size_t)b * SS * SS;
    const int tid = threadIdx.x, lane = tid & 31, wid = tid >> 5;
    const int L = lens[b];

    // zero marginal slab cooperatively (lower triangle / untouched cells must be 0)
    for (int t = rank * NT + tid; t < SS * SS; t += CS * NT) M[t] = 0.f;
    // diagonal init: redundant in every CTA (identical, deterministic)
    for (int i = tid; i < SS; i += NT) C[i * SPAD + i] = fsoftplus(R[i * SS + i]);
    __syncthreads();

    // ---------------- forward (inside), increasing width ----------------
    for (int w = 1; w < SS; ++w) {
        const int n  = SS - w;
        const int cb = (n * rank) / CS, ce = (n * (rank + 1)) / CS;  // cell slice, <=24
        const int c  = cb + wid;                                     // warp per cell, 1 pass
        if (c < ce) {
            const int i = c, j = c + w;
            const float rv = R[i * SS + j];           // prefetch (hides L2 latency)
            const int nu = (w + 31) >> 5;
            float v[6]; float m = NEGINF;
            #pragma unroll
            for (int u = 0; u < 6; ++u) {
                if (u < nu) {
                    int k = i + lane + (u << 5);
                    float x = (k < j) ? (C[i * SPAD + k] + C[(k + 1) * SPAD + j]) : NEGINF;
                    v[u] = x; m = fmaxf(m, x);
                }
            }
            #pragma unroll
            for (int o = 16; o; o >>= 1) m = fmaxf(m, __shfl_xor_sync(~0u, m, o));
            float s = 0.f;
            #pragma unroll
            for (int u = 0; u < 6; ++u) if (u < nu) s += __expf(v[u] - m);
            #pragma unroll
            for (int o = 16; o; o >>= 1) s += __shfl_xor_sync(~0u, s, o);
            const float val = fsoftplus(rv) + m + __logf(s);
            if (lane < CS) st_peer(smem_u32(&C[i * SPAD + j]), lane, val);  // broadcast
        }
        cluster_bar();
    }

    if (rank == 0 && tid == 0) Zout[b] = C[0 * SPAD + (L - 1)];

    // ---------------- backward (outside / marginals), decreasing width ----------------
    for (int w = SS - 1; w >= 0; --w) {
        const int n  = SS - w;
        const int cb = (n * rank) / CS, ce = (n * (rank + 1)) / CS;
        const int c  = cb + wid;
        if (c < ce) {
            const int i = c, j = c + w;
            const float aij = C[i * SPAD + j];
            const float rv  = R[i * SS + j];
            const int nR = SS - 1 - j;
            float s = 0.f;
            // right-extension parents: a[j+1,j'] + q[i,j']
            for (int t = lane; t < nR; t += 32) {
                const int j2 = j + 1 + t;
                s += __expf(aij + C[(j + 1) * SPAD + j2] + C[j2 * SPAD + i]);
            }
            // left-extension parents: a[i',i-1] + q[i',j]
            for (int t = lane; t < i; t += 32) {
                s += __expf(aij + C[t * SPAD + (i - 1)] + C[j * SPAD + t]);
            }
            #pragma unroll
            for (int o = 16; o; o >>= 1) s += __shfl_xor_sync(~0u, s, o);
            const float g = s + ((i == 0 && j == L - 1) ? 1.f : 0.f);
            if (lane == 0) M[i * SS + j] = g / (1.f + __expf(-rv));   // g * sigmoid(rv)
            if (i < j) {
                const float q = (g > 0.f) ? (__logf(g) - (aij - fsoftplus(rv))) : NEGINF;
                if (lane < CS) st_peer(smem_u32(&C[j * SPAD + i]), lane, q);
            }
        }
        cluster_bar();
    }
}

extern "C" void kernel_launch(void* const* d_in, const int* in_sizes, int n_in,
                              void* d_out, int out_size) {
    const float* rules = (const float*)d_in[0];   // (16,192,192,1) fp32
    const int*   lens  = (const int*)d_in[1];     // (16,) int32
    float* Z = (float*)d_out;                     // first 16 floats
    float* M = (float*)d_out + 16;                // then (16,192,192)

    const int smem = SS * SPAD * (int)sizeof(float);   // 148224 B
    cudaFuncSetAttribute(cky_kernel,
                         cudaFuncAttributeMaxDynamicSharedMemorySize, smem);
    (void)in_sizes; (void)n_in; (void)out_size;

    cky_kernel<<<16 * CS, NT, smem>>>(rules, lens, Z, M);
}

// round 13
// speedup vs baseline: 1.0052x; 1.0045x over previous
#include <cuda_runtime.h>
#include <cstdint>

#define SS   192
#define SPAD 193          // odd stride -> conflict-free column access
#define CS   8            // CTAs per batch (cluster)
#define NT   768          // 24 warps: >= max cells/CTA per width (ceil(191/8)=24)
#define NEGINF (-1e30f)

__device__ __forceinline__ float fsoftplus(float x) {
    return fmaxf(x, 0.f) + __logf(1.f + __expf(-fabsf(x)));
}
__device__ __forceinline__ uint32_t smem_u32(const void* p) {
    return (uint32_t)__cvta_generic_to_shared(p);
}
// store v into CTA `peer`'s smem at the same offset as local addr
__device__ __forceinline__ void st_peer(uint32_t laddr, int peer, float v) {
    uint32_t ra;
    asm volatile("mapa.shared::cluster.u32 %0, %1, %2;" : "=r"(ra) : "r"(laddr), "r"(peer));
    asm volatile("st.shared::cluster.f32 [%0], %1;" :: "r"(ra), "f"(v) : "memory");
}
__device__ __forceinline__ void cluster_bar() {
    asm volatile("barrier.cluster.arrive.aligned;" ::: "memory");
    asm volatile("barrier.cluster.wait.aligned;"   ::: "memory");
}

extern __shared__ float C[];   // [SS][SPAD]; upper tri = inside a, lower tri = q (bwd)

__global__ void __cluster_dims__(CS, 1, 1) __launch_bounds__(NT, 1)
cky_kernel(const float* __restrict__ rules, const int* __restrict__ lens,
           float* __restrict__ Zout, float* __restrict__ marg)
{
    const int b = blockIdx.x / CS;
    int rank; asm("mov.u32 %0, %%cluster_ctarank;" : "=r"(rank));
    const float* __restrict__ R = rules + (size_t)b * SS * SS;
    float* __restrict__ M = marg + (size_t)b * SS * SS;
    const int tid = threadIdx.x, lane = tid & 31, wid = tid >> 5;
    const int L = lens[b];

    // zero marginal slab cooperatively (lower triangle / untouched cells must be 0)
    for (int t = rank * NT + tid; t < SS * SS; t += CS * NT) M[t] = 0.f;
    // diagonal init: redundant in every CTA (identical, deterministic)
    for (int i = tid; i < SS; i += NT) C[i * SPAD + i] = fsoftplus(R[i * SS + i]);
    __syncthreads();

    // ---------------- forward (inside), increasing width ----------------
    for (int w = 1; w < SS; ++w) {
        const int n  = SS - w;
        const int cb = (n * rank) / CS, ce = (n * (rank + 1)) / CS;  // cell slice, <=24
        const int c  = cb + wid;                                     // warp per cell, 1 pass
        if (c < ce) {
            const int i = c, j = c + w;
            const float rv = R[i * SS + j];           // prefetch (hides L2 latency)
            const int nu = (w + 31) >> 5;
            float v[6]; float m = NEGINF;
            #pragma unroll
            for (int u = 0; u < 6; ++u) {
                if (u < nu) {
                    int k = i + lane + (u << 5);
                    float x = (k < j) ? (C[i * SPAD + k] + C[(k + 1) * SPAD + j]) : NEGINF;
                    v[u] = x; m = fmaxf(m, x);
                }
            }
            #pragma unroll
            for (int o = 16; o; o >>= 1) m = fmaxf(m, __shfl_xor_sync(~0u, m, o));
            float s = 0.f;
            #pragma unroll
            for (int u = 0; u < 6; ++u) if (u < nu) s += __expf(v[u] - m);
            #pragma unroll
            for (int o = 16; o; o >>= 1) s += __shfl_xor_sync(~0u, s, o);
            const float val = fsoftplus(rv) + m + __logf(s);
            if (lane < CS) st_peer(smem_u32(&C[i * SPAD + j]), lane, val);  // broadcast
        }
        cluster_bar();
    }

    if (rank == 0 && tid == 0) Zout[b] = C[0 * SPAD + (L - 1)];

    // ---------------- backward (outside / marginals), decreasing width ----------------
    for (int w = SS - 1; w >= 0; --w) {
        const int n  = SS - w;
        const int cb = (n * rank) / CS, ce = (n * (rank + 1)) / CS;
        const int c  = cb + wid;
        if (c < ce) {
            const int i = c, j = c + w;
            const float aij = C[i * SPAD + j];
            const float rv  = R[i * SS + j];
            const int nR = SS - 1 - j;
            float s = 0.f;
            // right-extension parents: a[j+1,j'] + q[i,j']
            for (int t = lane; t < nR; t += 32) {
                const int j2 = j + 1 + t;
                s += __expf(aij + C[(j + 1) * SPAD + j2] + C[j2 * SPAD + i]);
            }
            // left-extension parents: a[i',i-1] + q[i',j]
            for (int t = lane; t < i; t += 32) {
                s += __expf(aij + C[t * SPAD + (i - 1)] + C[j * SPAD + t]);
            }
            #pragma unroll
            for (int o = 16; o; o >>= 1) s += __shfl_xor_sync(~0u, s, o);
            const float g = s + ((i == 0 && j == L - 1) ? 1.f : 0.f);
            if (lane == 0) M[i * SS + j] = g / (1.f + __expf(-rv));   // g * sigmoid(rv)
            if (i < j) {
                const float q = (g > 0.f) ? (__logf(g) - (aij - fsoftplus(rv))) : NEGINF;
                if (lane < CS) st_peer(smem_u32(&C[j * SPAD + i]), lane, q);
            }
        }
        cluster_bar();
    }
}

extern "C" void kernel_launch(void* const* d_in, const int* in_sizes, int n_in,
                              void* d_out, int out_size) {
    const float* rules = (const float*)d_in[0];   // (16,192,192,1) fp32
    const int*   lens  = (const int*)d_in[1];     // (16,) int32
    float* Z = (float*)d_out;                     // first 16 floats
    float* M = (float*)d_out + 16;                // then (16,192,192)

    const int smem = SS * SPAD * (int)sizeof(float);   // 148224 B
    cudaFuncSetAttribute(cky_kernel,
                         cudaFuncAttributeMaxDynamicSharedMemorySize, smem);
    (void)in_sizes; (void)n_in; (void)out_size;

    cky_kernel<<<16 * CS, NT, smem>>>(rules, lens, Z, M);
}